// round 16
// baseline (speedup 1.0000x reference)
#include <cuda_runtime.h>

#define DD 64
#define H_ 256
#define W_ 512
#define HW_ (H_ * W_)
#define B_ 8
#define NPIX (B_ * HW_)
#define VEC 4
#define TPB 128
#define NTILES (NPIX / VEC / TPB)      // 2048 tiles
#define GRID 1184                       // <= one-wave capacity (148*8); stealing balances

__device__ double g_part[NTILES];       // per-TILE partials -> deterministic finalize
__device__ unsigned int g_pcnt[NTILES];
__device__ unsigned int g_tile = GRID;  // work counter; last block resets each launch
__device__ unsigned int g_ticket;       // zero; last block resets

__global__ __launch_bounds__(TPB, 8) void sce_main(const float* __restrict__ sim,
                                                   const float* __restrict__ gt,
                                                   float* __restrict__ out) {
    int tid = threadIdx.x;
    int lane = tid & 31;
    int warp = tid >> 5;

    const float E1  = 2.718281828459045f;    // e
    const float IE1 = 0.3678794411714423f;   // 1/e
    const float C1  = 0.15651764274966565f;  // 1/(e^2-1)
    const float C2  = 1.1565176427496657f;   // 1/(1-e^-2)
    const unsigned mask = 0xffffffffu;

    __shared__ unsigned int s_next;
    __shared__ double ssum[TPB / 32];
    __shared__ unsigned int scnt[TPB / 32];
    __shared__ int s_last;

    auto tilebase = [&](int t) -> const float* {
        long long base = (long long)t * (TPB * VEC) + tid * VEC;
        int b = (int)(base / HW_);
        int hw = (int)(base - (long long)b * HW_);
        return sim + (long long)b * DD * HW_ + hw;
    };

    int cur = blockIdx.x;
    const float* sb_cur = tilebase(cur);

    // Prologue: first tile's planes 0..3
    float4 bufA[4], bufB[4];
#pragma unroll
    for (int k = 0; k < 4; ++k)
        bufA[k] = __ldcs(reinterpret_cast<const float4*>(sb_cur + (long long)k * HW_));

    while (true) {
        // Draw next tile id early (prefetch target at drain time)
        if (tid == 0) s_next = atomicAdd(&g_tile, 1u);
        __syncthreads();
        unsigned next = s_next;
        bool have_next = next < NTILES;
        const float* sb_next = have_next ? tilebase((int)next) : sb_cur;

        long long gbase = (long long)cur * (TPB * VEC) + tid * VEC;
        float4 g4 = *reinterpret_cast<const float4*>(gt + gbase);
        float gts[VEC] = {g4.x, g4.y, g4.z, g4.w};

        // u_d = e^{(2d-gt)/2}, v_d = e^{(gt-2d)/2}; p_d = exp(-|gt-2d|) = min(u,v)^2
        float u[VEC], v[VEC], esum[VEC], pts[VEC];
#pragma unroll
        for (int j = 0; j < VEC; ++j) {
            float hg = 0.5f * gts[j];
            u[j] = __expf(-hg);
            v[j] = __expf(hg);
            esum[j] = 0.f; pts[j] = 0.f;
        }

        auto body = [&](float4 s4) {
            float sv[VEC] = {s4.x, s4.y, s4.z, s4.w};
#pragma unroll
            for (int j = 0; j < VEC; ++j) {
                float s = sv[j];
                esum[j] += __expf(s);
                float mm = fminf(u[j], v[j]);
                pts[j] = fmaf(mm * mm, s, pts[j]);
                u[j] *= E1;
                v[j] *= IE1;
            }
        };

        const float* sbase = sb_cur;
        // A/B ping-pong double buffer, batch = 4 planes (proven structure)
#pragma unroll 1
        for (int db = 0; db < DD - 8; db += 8) {
#pragma unroll
            for (int k = 0; k < 4; ++k)
                bufB[k] = __ldcs(reinterpret_cast<const float4*>(sbase + (long long)(db + 4 + k) * HW_));
#pragma unroll
            for (int k = 0; k < 4; ++k) body(bufA[k]);
#pragma unroll
            for (int k = 0; k < 4; ++k)
                bufA[k] = __ldcs(reinterpret_cast<const float4*>(sbase + (long long)(db + 8 + k) * HW_));
#pragma unroll
            for (int k = 0; k < 4; ++k) body(bufB[k]);
        }
        // bufA holds 56..59; load 60..63, consume A, cross-tile prefetch, consume B.
#pragma unroll
        for (int k = 0; k < 4; ++k)
            bufB[k] = __ldcs(reinterpret_cast<const float4*>(sbase + (long long)(DD - 4 + k) * HW_));
#pragma unroll
        for (int k = 0; k < 4; ++k) body(bufA[k]);
        if (have_next) {
#pragma unroll
            for (int k = 0; k < 4; ++k)
                bufA[k] = __ldcs(reinterpret_cast<const float4*>(sb_next + (long long)k * HW_));
        }
#pragma unroll
        for (int k = 0; k < 4; ++k) body(bufB[k]);

        // Tile epilogue: closed-form ptn, entropy
        double lsum = 0.0;
        unsigned int lcnt = 0u;
#pragma unroll
        for (int j = 0; j < VEC; ++j) {
            if (isfinite(gts[j])) {
                float gtv = gts[j];
                float m0 = floorf(gtv * 0.5f);
                float tt = fmaf(-2.0f, m0, gtv);
                float et2 = __expf(tt - 2.0f);
                float e2t = 1.0f / et2;
                float eng = __expf(-gtv);
                float wsq = __expf(gtv - 128.0f);
                float ptn = (e2t - eng) * C1 + (et2 - wsq) * C2;
                float ent = __logf(esum[j]) - pts[j] / ptn;
                lsum += (double)ent;
                lcnt++;
            }
        }

        // Per-tile CTA reduction -> g_part[cur] (tile-indexed: deterministic finalize)
#pragma unroll
        for (int o = 16; o > 0; o >>= 1) {
            lsum += __shfl_down_sync(mask, lsum, o);
            lcnt += __shfl_down_sync(mask, lcnt, o);
        }
        __syncthreads();                       // protect ssum/scnt reuse
        if (lane == 0) { ssum[warp] = lsum; scnt[warp] = lcnt; }
        __syncthreads();
        if (warp == 0) {
            lsum = (lane < TPB / 32) ? ssum[lane] : 0.0;
            lcnt = (lane < TPB / 32) ? scnt[lane] : 0u;
#pragma unroll
            for (int o = 2; o > 0; o >>= 1) {
                lsum += __shfl_down_sync(mask, lsum, o);
                lcnt += __shfl_down_sync(mask, lcnt, o);
            }
            if (lane == 0) {
                g_part[cur] = lsum;
                g_pcnt[cur] = lcnt;
            }
        }

        if (!have_next) break;
        cur = (int)next;
        sb_cur = sb_next;
    }

    // CTA-completion ticket; last CTA finalizes deterministically over all tiles.
    if (tid == 0) {
        __threadfence();
        unsigned int t = atomicAdd(&g_ticket, 1u);
        s_last = (t == GRID - 1);
    }
    __syncthreads();

    if (s_last) {
        double s = 0.0;
        unsigned int c = 0u;
#pragma unroll 4
        for (int i = tid; i < NTILES; i += TPB) {
            s += __ldcg(&g_part[i]);
            c += __ldcg(&g_pcnt[i]);
        }
#pragma unroll
        for (int o = 16; o > 0; o >>= 1) {
            s += __shfl_down_sync(mask, s, o);
            c += __shfl_down_sync(mask, c, o);
        }
        __syncthreads();
        if (lane == 0) { ssum[warp] = s; scnt[warp] = c; }
        __syncthreads();
        if (warp == 0) {
            s = (lane < TPB / 32) ? ssum[lane] : 0.0;
            c = (lane < TPB / 32) ? scnt[lane] : 0u;
#pragma unroll
            for (int o = 2; o > 0; o >>= 1) {
                s += __shfl_down_sync(mask, s, o);
                c += __shfl_down_sync(mask, c, o);
            }
            if (lane == 0) {
                out[0] = (float)(s / (double)c);
                g_ticket = 0u;
                g_tile = GRID;                 // reset work counter for next replay
                __threadfence();
            }
        }
    }
}

extern "C" void kernel_launch(void* const* d_in, const int* in_sizes, int n_in,
                              void* d_out, int out_size) {
    const float* sim = (const float*)d_in[0];
    const float* gt  = (const float*)d_in[1];
    float* out = (float*)d_out;

    sce_main<<<GRID, TPB>>>(sim, gt, out);
}